// round 5
// baseline (speedup 1.0000x reference)
#include <cuda_runtime.h>
#include <math.h>

#define Bsz   2
#define Tseq  2048
#define Cdim  1024
#define Hn    16
#define HD    64
#define BHn   (Bsz*Hn)          // 32
#define MROWS (Bsz*Tseq)        // 4096
#define QKVN  (3*Cdim)          // 3072

// ---- scratch (static device globals; no allocation) ----
__device__ float g_qkv[(size_t)MROWS * QKVN];     // [B*T, 3C]
__device__ float g_Q[(size_t)BHn * Tseq * HD];    // [B,H,T,hd]
__device__ float g_K[(size_t)BHn * Tseq * HD];
__device__ float g_V[(size_t)BHn * Tseq * HD];
__device__ float g_att[(size_t)MROWS * Cdim];     // [B,T,C] pre-projection
__device__ float g_cos[Tseq * 32];                // rope tables [t][j]
__device__ float g_sin[Tseq * 32];

// ======================================================================
// C[M,N] = A[M,K] * B[N,K]^T    (both K-major, fp32)
// 128x128 tile, BK=16, 256 threads, 8x8 microtile, reg-prefetch pipeline.
// MODE 0: A = x (param), C = g_qkv.   MODE 1: A = g_att, C = out (param).
// ======================================================================
template<int MODE>
__global__ void __launch_bounds__(256) gemm_nt(const float* __restrict__ Aext,
                                               const float* __restrict__ Bm,
                                               float* __restrict__ Cext,
                                               int M, int N, int K)
{
    const float* A  = (MODE == 0) ? Aext : (const float*)g_att;
    float*       Cm = (MODE == 0) ? (float*)g_qkv : Cext;

    const int BK = 16;
    __shared__ float As[BK][128];   // [k][m]
    __shared__ float Bs[BK][128];   // [k][n]

    const int tid = threadIdx.x;
    const int tx = tid & 15;            // n group
    const int ty = tid >> 4;            // m group
    const int rowBase = blockIdx.y * 128;
    const int colBase = blockIdx.x * 128;
    const int lr = tid >> 1;            // 0..127
    const int lc = (tid & 1) << 3;      // 0 or 8

    const float* Aptr = A + (size_t)(rowBase + lr) * K + lc;
    const float* Bptr = Bm + (size_t)(colBase + lr) * K + lc;

    float acc[8][8];
    #pragma unroll
    for (int i = 0; i < 8; ++i)
        #pragma unroll
        for (int j = 0; j < 8; ++j) acc[i][j] = 0.f;

    // prefetch first tile into registers
    float4 pa0 = *reinterpret_cast<const float4*>(Aptr);
    float4 pa1 = *reinterpret_cast<const float4*>(Aptr + 4);
    float4 pb0 = *reinterpret_cast<const float4*>(Bptr);
    float4 pb1 = *reinterpret_cast<const float4*>(Bptr + 4);

    for (int k0 = 0; k0 < K; k0 += BK) {
        As[lc+0][lr]=pa0.x; As[lc+1][lr]=pa0.y; As[lc+2][lr]=pa0.z; As[lc+3][lr]=pa0.w;
        As[lc+4][lr]=pa1.x; As[lc+5][lr]=pa1.y; As[lc+6][lr]=pa1.z; As[lc+7][lr]=pa1.w;
        Bs[lc+0][lr]=pb0.x; Bs[lc+1][lr]=pb0.y; Bs[lc+2][lr]=pb0.z; Bs[lc+3][lr]=pb0.w;
        Bs[lc+4][lr]=pb1.x; Bs[lc+5][lr]=pb1.y; Bs[lc+6][lr]=pb1.z; Bs[lc+7][lr]=pb1.w;
        __syncthreads();

        if (k0 + BK < K) {   // issue next-tile loads; they fly during compute
            pa0 = *reinterpret_cast<const float4*>(Aptr + k0 + BK);
            pa1 = *reinterpret_cast<const float4*>(Aptr + k0 + BK + 4);
            pb0 = *reinterpret_cast<const float4*>(Bptr + k0 + BK);
            pb1 = *reinterpret_cast<const float4*>(Bptr + k0 + BK + 4);
        }

        #pragma unroll
        for (int kk = 0; kk < BK; ++kk) {
            float4 a0 = *reinterpret_cast<const float4*>(&As[kk][ty << 3]);
            float4 a1 = *reinterpret_cast<const float4*>(&As[kk][(ty << 3) + 4]);
            float4 b0 = *reinterpret_cast<const float4*>(&Bs[kk][tx << 3]);
            float4 b1 = *reinterpret_cast<const float4*>(&Bs[kk][(tx << 3) + 4]);
            float ar[8] = {a0.x,a0.y,a0.z,a0.w,a1.x,a1.y,a1.z,a1.w};
            float br[8] = {b0.x,b0.y,b0.z,b0.w,b1.x,b1.y,b1.z,b1.w};
            #pragma unroll
            for (int i = 0; i < 8; ++i)
                #pragma unroll
                for (int j = 0; j < 8; ++j)
                    acc[i][j] = fmaf(ar[i], br[j], acc[i][j]);
        }
        __syncthreads();
    }

    #pragma unroll
    for (int i = 0; i < 8; ++i) {
        float* crow = Cm + (size_t)(rowBase + (ty << 3) + i) * N + colBase + (tx << 3);
        *reinterpret_cast<float4*>(crow) =
            make_float4(acc[i][0], acc[i][1], acc[i][2], acc[i][3]);
        *reinterpret_cast<float4*>(crow + 4) =
            make_float4(acc[i][4], acc[i][5], acc[i][6], acc[i][7]);
    }
}

// ======================================================================
// RoPE tables: once per launch, double precision.
// ======================================================================
__global__ void rope_table_kernel()
{
    int idx = blockIdx.x * blockDim.x + threadIdx.x;   // [0, Tseq*32)
    int j = idx & 31;
    int t = idx >> 5;
    double invf = exp(-(double)j * (9.210340371976184 / 32.0)); // ln(10000)
    double sd, cd;
    sincos((double)t * invf, &sd, &cd);
    g_cos[idx] = (float)cd;
    g_sin[idx] = (float)sd;
}

// ======================================================================
// RoPE + QKV split/transpose.
// ======================================================================
__global__ void rope_kernel()
{
    int idx = blockIdx.x * blockDim.x + threadIdx.x;
    int j = idx & 31;
    int h = (idx >> 5) & (Hn - 1);
    int t = (idx >> 9) & (Tseq - 1);
    int b = idx >> 20;

    size_t base = (size_t)(b * Tseq + t) * QKVN;
    int qo = h * HD + j;

    float c = g_cos[(t << 5) + j];
    float s = g_sin[(t << 5) + j];

    size_t o = ((size_t)(b * Hn + h) * Tseq + t) * HD + j;

    float q0 = g_qkv[base + qo];
    float q1 = g_qkv[base + qo + 32];
    g_Q[o]      = q0 * c - q1 * s;
    g_Q[o + 32] = q1 * c + q0 * s;

    float k0 = g_qkv[base + Cdim + qo];
    float k1 = g_qkv[base + Cdim + qo + 32];
    g_K[o]      = k0 * c - k1 * s;
    g_K[o + 32] = k1 * c + k0 * s;

    g_V[o]      = g_qkv[base + 2 * Cdim + qo];
    g_V[o + 32] = g_qkv[base + 2 * Cdim + qo + 32];
}

// ======================================================================
// Flash attention, fp32, causal.
// Block = 256 threads = 128 query rows of one (b,h); 2 threads per row,
// each owns 32 head dims. Bc=32 key tiles. Partner lanes (xor 1) combine
// QK partials via shfl. smem = 8+8+16 = 32KB -> 2 blocks/SM, 16 warps.
// ======================================================================
#define ABC 32          // keys per tile
__global__ void __launch_bounds__(256, 2) attn_kernel()
{
    const int qblk = blockIdx.x;     // 0..15  (128 rows each)
    const int bh   = blockIdx.y;     // 0..31
    const int tid  = threadIdx.x;    // 0..255
    const int r    = tid >> 1;       // local row 0..127
    const int half = tid & 1;        // which 32-dim half
    const int qi   = qblk * 128 + r;

    float q[32], acc[32];
    {
        const float4* q4 = reinterpret_cast<const float4*>(
            g_Q + ((size_t)bh * Tseq + qi) * HD + half * 32);
        #pragma unroll
        for (int d4 = 0; d4 < 8; ++d4) {
            float4 v = q4[d4];
            q[4*d4+0] = v.x * 0.125f;   // 1/sqrt(64)
            q[4*d4+1] = v.y * 0.125f;
            q[4*d4+2] = v.z * 0.125f;
            q[4*d4+3] = v.w * 0.125f;
        }
    }
    #pragma unroll
    for (int d = 0; d < 32; ++d) acc[d] = 0.f;
    float m = -1e30f, l = 0.f;

    __shared__ float ks[ABC][HD];        // 8KB
    __shared__ float vs[ABC][HD];        // 8KB
    __shared__ float sbuf[ABC][128];     // 16KB

    const float4* Kp4 = reinterpret_cast<const float4*>(g_K + (size_t)bh * Tseq * HD);
    const float4* Vp4 = reinterpret_cast<const float4*>(g_V + (size_t)bh * Tseq * HD);

    const int ntiles = qblk * 4 + 4;     // covers keys [0, qblk*128+128)

    for (int t0 = 0; t0 < ntiles; ++t0) {
        __syncthreads();
        {   // 512 float4 per array, 256 threads -> 2 each, coalesced
            const float4* Ksrc = Kp4 + (size_t)t0 * ABC * 16;
            const float4* Vsrc = Vp4 + (size_t)t0 * ABC * 16;
            float4* kd = reinterpret_cast<float4*>(&ks[0][0]);
            float4* vd = reinterpret_cast<float4*>(&vs[0][0]);
            kd[tid]       = Ksrc[tid];
            kd[tid + 256] = Ksrc[tid + 256];
            vd[tid]       = Vsrc[tid];
            vd[tid + 256] = Vsrc[tid + 256];
        }
        __syncthreads();

        const int kbase = t0 * ABC;

        // ---- QK scores ----
        float tmax = -1e30f;
        #pragma unroll 4
        for (int j = 0; j < ABC; ++j) {
            const float4* kr = reinterpret_cast<const float4*>(ks[j]) + half * 8;
            float s0 = 0.f, s1 = 0.f, s2 = 0.f, s3 = 0.f;
            #pragma unroll
            for (int d4 = 0; d4 < 8; ++d4) {
                float4 kv = kr[d4];
                s0 = fmaf(q[4*d4+0], kv.x, s0);
                s1 = fmaf(q[4*d4+1], kv.y, s1);
                s2 = fmaf(q[4*d4+2], kv.z, s2);
                s3 = fmaf(q[4*d4+3], kv.w, s3);
            }
            float part = (s0 + s1) + (s2 + s3);
            float s = part + __shfl_xor_sync(0xffffffffu, part, 1);
            if (kbase + j > qi) s = -1e30f;        // causal mask
            if (half == 0) sbuf[j][r] = s;
            tmax = fmaxf(tmax, s);
        }
        __syncwarp();

        float mnew = fmaxf(m, tmax);
        float corr = __expf(m - mnew);
        l *= corr;
        #pragma unroll
        for (int d = 0; d < 32; ++d) acc[d] *= corr;

        // ---- PV accumulate ----
        #pragma unroll 4
        for (int j = 0; j < ABC; ++j) {
            float p = __expf(sbuf[j][r] - mnew);
            l += p;
            const float4* vr = reinterpret_cast<const float4*>(vs[j]) + half * 8;
            #pragma unroll
            for (int d4 = 0; d4 < 8; ++d4) {
                float4 vv = vr[d4];
                acc[4*d4+0] = fmaf(p, vv.x, acc[4*d4+0]);
                acc[4*d4+1] = fmaf(p, vv.y, acc[4*d4+1]);
                acc[4*d4+2] = fmaf(p, vv.z, acc[4*d4+2]);
                acc[4*d4+3] = fmaf(p, vv.w, acc[4*d4+3]);
            }
        }
        m = mnew;
        __syncwarp();
    }

    const float inv = 1.f / l;
    const int b = bh >> 4;
    const int h = bh & 15;
    float4* op = reinterpret_cast<float4*>(
        g_att + (size_t)(b * Tseq + qi) * Cdim + h * HD + half * 32);
    #pragma unroll
    for (int d4 = 0; d4 < 8; ++d4)
        op[d4] = make_float4(acc[4*d4+0]*inv, acc[4*d4+1]*inv,
                             acc[4*d4+2]*inv, acc[4*d4+3]*inv);
}

// ======================================================================
extern "C" void kernel_launch(void* const* d_in, const int* in_sizes, int n_in,
                              void* d_out, int out_size)
{
    const float* x      = (const float*)d_in[0];
    const float* w_attn = (const float*)d_in[1];
    const float* w_proj = (const float*)d_in[2];
    float* out = (float*)d_out;

    // 0) rope tables (tiny)
    rope_table_kernel<<<(Tseq * 32) / 256, 256>>>();

    // 1) QKV = x @ w_attn^T -> g_qkv
    gemm_nt<0><<<dim3(QKVN / 128, MROWS / 128), 256>>>(x, w_attn, nullptr,
                                                       MROWS, QKVN, Cdim);

    // 2) RoPE + split to [B,H,T,hd]
    rope_kernel<<<(Bsz * Tseq * Hn * 32) / 256, 256>>>();

    // 3) causal flash attention -> g_att [B,T,C]
    attn_kernel<<<dim3(Tseq / 128, BHn), 256>>>();

    // 4) out = g_att @ w_proj^T
    gemm_nt<1><<<dim3(Cdim / 128, MROWS / 128), 256>>>(nullptr, w_proj, out,
                                                       MROWS, Cdim, Cdim);
}

// round 6
// speedup vs baseline: 1.5339x; 1.5339x over previous
#include <cuda_runtime.h>
#include <math.h>

#define Bsz   2
#define Tseq  2048
#define Cdim  1024
#define Hn    16
#define HD    64
#define BHn   (Bsz*Hn)          // 32
#define MROWS (Bsz*Tseq)        // 4096
#define QKVN  (3*Cdim)          // 3072

// ---- scratch (static device globals; no allocation) ----
__device__ float g_qkv[(size_t)MROWS * QKVN];     // [B*T, 3C]
__device__ float g_Q[(size_t)BHn * Tseq * HD];    // [B,H,T,hd]
__device__ float g_K[(size_t)BHn * Tseq * HD];
__device__ float g_V[(size_t)BHn * Tseq * HD];
__device__ float g_att[(size_t)MROWS * Cdim];     // [B,T,C] pre-projection
__device__ float g_cos[Tseq * 32];                // rope tables [t][j]
__device__ float g_sin[Tseq * 32];

// ======================================================================
// C[M,N] = A[M,K] * B[N,K]^T  (fp32, K-major). 128x128 tile, BK=16,
// 256 threads, 8x8 microtile, register-prefetch pipeline.
// ======================================================================
template<int MODE>
__global__ void __launch_bounds__(256) gemm_nt(const float* __restrict__ Aext,
                                               const float* __restrict__ Bm,
                                               float* __restrict__ Cext,
                                               int M, int N, int K)
{
    const float* A  = (MODE == 0) ? Aext : (const float*)g_att;
    float*       Cm = (MODE == 0) ? (float*)g_qkv : Cext;

    const int BK = 16;
    __shared__ float As[BK][128];
    __shared__ float Bs[BK][128];

    const int tid = threadIdx.x;
    const int tx = tid & 15;
    const int ty = tid >> 4;
    const int rowBase = blockIdx.y * 128;
    const int colBase = blockIdx.x * 128;
    const int lr = tid >> 1;
    const int lc = (tid & 1) << 3;

    const float* Aptr = A + (size_t)(rowBase + lr) * K + lc;
    const float* Bptr = Bm + (size_t)(colBase + lr) * K + lc;

    float acc[8][8];
    #pragma unroll
    for (int i = 0; i < 8; ++i)
        #pragma unroll
        for (int j = 0; j < 8; ++j) acc[i][j] = 0.f;

    float4 pa0 = *reinterpret_cast<const float4*>(Aptr);
    float4 pa1 = *reinterpret_cast<const float4*>(Aptr + 4);
    float4 pb0 = *reinterpret_cast<const float4*>(Bptr);
    float4 pb1 = *reinterpret_cast<const float4*>(Bptr + 4);

    for (int k0 = 0; k0 < K; k0 += BK) {
        As[lc+0][lr]=pa0.x; As[lc+1][lr]=pa0.y; As[lc+2][lr]=pa0.z; As[lc+3][lr]=pa0.w;
        As[lc+4][lr]=pa1.x; As[lc+5][lr]=pa1.y; As[lc+6][lr]=pa1.z; As[lc+7][lr]=pa1.w;
        Bs[lc+0][lr]=pb0.x; Bs[lc+1][lr]=pb0.y; Bs[lc+2][lr]=pb0.z; Bs[lc+3][lr]=pb0.w;
        Bs[lc+4][lr]=pb1.x; Bs[lc+5][lr]=pb1.y; Bs[lc+6][lr]=pb1.z; Bs[lc+7][lr]=pb1.w;
        __syncthreads();

        if (k0 + BK < K) {
            pa0 = *reinterpret_cast<const float4*>(Aptr + k0 + BK);
            pa1 = *reinterpret_cast<const float4*>(Aptr + k0 + BK + 4);
            pb0 = *reinterpret_cast<const float4*>(Bptr + k0 + BK);
            pb1 = *reinterpret_cast<const float4*>(Bptr + k0 + BK + 4);
        }

        #pragma unroll
        for (int kk = 0; kk < BK; ++kk) {
            float4 a0 = *reinterpret_cast<const float4*>(&As[kk][ty << 3]);
            float4 a1 = *reinterpret_cast<const float4*>(&As[kk][(ty << 3) + 4]);
            float4 b0 = *reinterpret_cast<const float4*>(&Bs[kk][tx << 3]);
            float4 b1 = *reinterpret_cast<const float4*>(&Bs[kk][(tx << 3) + 4]);
            float ar[8] = {a0.x,a0.y,a0.z,a0.w,a1.x,a1.y,a1.z,a1.w};
            float br[8] = {b0.x,b0.y,b0.z,b0.w,b1.x,b1.y,b1.z,b1.w};
            #pragma unroll
            for (int i = 0; i < 8; ++i)
                #pragma unroll
                for (int j = 0; j < 8; ++j)
                    acc[i][j] = fmaf(ar[i], br[j], acc[i][j]);
        }
        __syncthreads();
    }

    #pragma unroll
    for (int i = 0; i < 8; ++i) {
        float* crow = Cm + (size_t)(rowBase + (ty << 3) + i) * N + colBase + (tx << 3);
        *reinterpret_cast<float4*>(crow) =
            make_float4(acc[i][0], acc[i][1], acc[i][2], acc[i][3]);
        *reinterpret_cast<float4*>(crow + 4) =
            make_float4(acc[i][4], acc[i][5], acc[i][6], acc[i][7]);
    }
}

// ======================================================================
// RoPE tables (double precision, tiny)
// ======================================================================
__global__ void rope_table_kernel()
{
    int idx = blockIdx.x * blockDim.x + threadIdx.x;
    int j = idx & 31;
    int t = idx >> 5;
    double invf = exp(-(double)j * (9.210340371976184 / 32.0));
    double sd, cd;
    sincos((double)t * invf, &sd, &cd);
    g_cos[idx] = (float)cd;
    g_sin[idx] = (float)sd;
}

// ======================================================================
// RoPE + QKV split/transpose
// ======================================================================
__global__ void rope_kernel()
{
    int idx = blockIdx.x * blockDim.x + threadIdx.x;
    int j = idx & 31;
    int h = (idx >> 5) & (Hn - 1);
    int t = (idx >> 9) & (Tseq - 1);
    int b = idx >> 20;

    size_t base = (size_t)(b * Tseq + t) * QKVN;
    int qo = h * HD + j;

    float c = g_cos[(t << 5) + j];
    float s = g_sin[(t << 5) + j];

    size_t o = ((size_t)(b * Hn + h) * Tseq + t) * HD + j;

    float q0 = g_qkv[base + qo];
    float q1 = g_qkv[base + qo + 32];
    g_Q[o]      = q0 * c - q1 * s;
    g_Q[o + 32] = q1 * c + q0 * s;

    float k0 = g_qkv[base + Cdim + qo];
    float k1 = g_qkv[base + Cdim + qo + 32];
    g_K[o]      = k0 * c - k1 * s;
    g_K[o + 32] = k1 * c + k0 * s;

    g_V[o]      = g_qkv[base + 2 * Cdim + qo];
    g_V[o + 32] = g_qkv[base + 2 * Cdim + qo + 32];
}

// ======================================================================
// Flash attention as two microtiled GEMMs per tile. fp32, causal.
// Block: 256 threads, Br=Bc=64. Thread (ty,tx) owns 4 rows x 4 cols.
// qs [d][i] (Q^T, pre-scaled), ks/sbuf union, vs [j][e]. smem = 48KB.
// Softmax state (m,l) in registers, replicated across the 16-lane tx
// group via shfl reductions.
// ======================================================================
__global__ void __launch_bounds__(256) attn_kernel()
{
    __shared__ float qs[64 * 64];    // [d][i]
    __shared__ float ksb[64 * 64];   // K^T [d][j] during QK; P [j][i] during PV
    __shared__ float vs[64 * 64];    // [j][e]

    const int qtile = gridDim.x - 1 - blockIdx.x;   // longest blocks first
    const int bh    = blockIdx.y;
    const int tid   = threadIdx.x;
    const int tx = tid & 15;         // col group (keys / dims)
    const int ty = tid >> 4;         // row group (queries)

    const float* Qb = g_Q + ((size_t)bh * Tseq + qtile * 64) * HD;
    const float* Kb = g_K + (size_t)bh * Tseq * HD;
    const float* Vb = g_V + (size_t)bh * Tseq * HD;

    // ---- load Q tile transposed into qs[d][i], folding the 1/8 scale ----
    {
        const int d4 = tid >> 5;     // 0..7
        const int i  = tid & 31;     // row (lane) -> conflict-free STS
        #pragma unroll
        for (int ii = 0; ii < 2; ++ii) {
            #pragma unroll
            for (int dd = 0; dd < 2; ++dd) {
                int row = i + ii * 32;
                int d0  = (d4 + dd * 8) * 4;
                float4 v = *reinterpret_cast<const float4*>(Qb + row * HD + d0);
                qs[(d0 + 0) * 64 + row] = v.x * 0.125f;
                qs[(d0 + 1) * 64 + row] = v.y * 0.125f;
                qs[(d0 + 2) * 64 + row] = v.z * 0.125f;
                qs[(d0 + 3) * 64 + row] = v.w * 0.125f;
            }
        }
    }

    float acc[4][4];
    #pragma unroll
    for (int r = 0; r < 4; ++r)
        #pragma unroll
        for (int e = 0; e < 4; ++e) acc[r][e] = 0.f;
    float m[4] = {-1e30f, -1e30f, -1e30f, -1e30f};
    float l[4] = {0.f, 0.f, 0.f, 0.f};

    for (int t0 = 0; t0 <= qtile; ++t0) {
        const int kbase = t0 * 64;

        // ---- load K tile transposed -> ksb[d][j]; V tile -> vs[j][e] ----
        __syncthreads();
        {
            const int d4 = tid >> 5;
            const int j  = tid & 31;
            #pragma unroll
            for (int jj = 0; jj < 2; ++jj) {
                #pragma unroll
                for (int dd = 0; dd < 2; ++dd) {
                    int row = j + jj * 32;
                    int d0  = (d4 + dd * 8) * 4;
                    float4 v = *reinterpret_cast<const float4*>(
                        Kb + (size_t)(kbase + row) * HD + d0);
                    ksb[(d0 + 0) * 64 + row] = v.x;
                    ksb[(d0 + 1) * 64 + row] = v.y;
                    ksb[(d0 + 2) * 64 + row] = v.z;
                    ksb[(d0 + 3) * 64 + row] = v.w;
                }
            }
            const int f  = tid & 15;
            const int j0 = tid >> 4;
            #pragma unroll
            for (int jj = 0; jj < 4; ++jj) {
                int row = j0 + jj * 16;
                float4 v = *reinterpret_cast<const float4*>(
                    Vb + (size_t)(kbase + row) * HD + 4 * f);
                *reinterpret_cast<float4*>(vs + row * 64 + 4 * f) = v;
            }
        }
        __syncthreads();

        // ---- QK microtile GEMM: S[4][4] over d=0..63 ----
        float S[4][4];
        #pragma unroll
        for (int r = 0; r < 4; ++r)
            #pragma unroll
            for (int c = 0; c < 4; ++c) S[r][c] = 0.f;

        #pragma unroll 4
        for (int d = 0; d < 64; ++d) {
            float4 a = *reinterpret_cast<const float4*>(qs + d * 64 + 4 * ty);
            float4 b = *reinterpret_cast<const float4*>(ksb + d * 64 + 4 * tx);
            float ar[4] = {a.x, a.y, a.z, a.w};
            float br[4] = {b.x, b.y, b.z, b.w};
            #pragma unroll
            for (int r = 0; r < 4; ++r)
                #pragma unroll
                for (int c = 0; c < 4; ++c)
                    S[r][c] = fmaf(ar[r], br[c], S[r][c]);
        }

        // ---- causal mask on the diagonal tile ----
        if (t0 == qtile) {
            #pragma unroll
            for (int r = 0; r < 4; ++r)
                #pragma unroll
                for (int c = 0; c < 4; ++c)
                    if (4 * tx + c > 4 * ty + r) S[r][c] = -1e30f;
        }

        // ---- online softmax: row stats via 16-lane shfl reductions ----
        #pragma unroll
        for (int r = 0; r < 4; ++r) {
            float vmax = fmaxf(fmaxf(S[r][0], S[r][1]), fmaxf(S[r][2], S[r][3]));
            #pragma unroll
            for (int mk = 1; mk < 16; mk <<= 1)
                vmax = fmaxf(vmax, __shfl_xor_sync(0xffffffffu, vmax, mk));
            float mn = fmaxf(m[r], vmax);
            float corr = __expf(m[r] - mn);
            m[r] = mn;
            l[r] *= corr;
            #pragma unroll
            for (int e = 0; e < 4; ++e) acc[r][e] *= corr;
            float lsum = 0.f;
            #pragma unroll
            for (int c = 0; c < 4; ++c) {
                S[r][c] = __expf(S[r][c] - mn);
                lsum += S[r][c];
            }
            #pragma unroll
            for (int mk = 1; mk < 16; mk <<= 1)
                lsum += __shfl_xor_sync(0xffffffffu, lsum, mk);
            l[r] += lsum;
        }

        // ---- write P into sbuf (= ksb region) as [j][i], swizzled ----
        __syncthreads();
        #pragma unroll
        for (int c = 0; c < 4; ++c) {
            int j = 4 * tx + c;
            int col = (4 * ty + 4 * j) & 63;
            *reinterpret_cast<float4*>(ksb + j * 64 + col) =
                make_float4(S[0][c], S[1][c], S[2][c], S[3][c]);
        }
        __syncthreads();

        // ---- PV microtile GEMM: acc[4][4] over j=0..63 ----
        #pragma unroll 4
        for (int j = 0; j < 64; ++j) {
            int col = (4 * ty + 4 * j) & 63;
            float4 p = *reinterpret_cast<const float4*>(ksb + j * 64 + col);
            float4 v = *reinterpret_cast<const float4*>(vs + j * 64 + 4 * tx);
            float pr[4] = {p.x, p.y, p.z, p.w};
            float vr[4] = {v.x, v.y, v.z, v.w};
            #pragma unroll
            for (int r = 0; r < 4; ++r)
                #pragma unroll
                for (int e = 0; e < 4; ++e)
                    acc[r][e] = fmaf(pr[r], vr[e], acc[r][e]);
        }
    }

    // ---- output ----
    const int b = bh >> 4;
    const int h = bh & 15;
    #pragma unroll
    for (int r = 0; r < 4; ++r) {
        float inv = 1.f / l[r];
        int qi = qtile * 64 + 4 * ty + r;
        float* op = g_att + (size_t)(b * Tseq + qi) * Cdim + h * HD + 4 * tx;
        *reinterpret_cast<float4*>(op) =
            make_float4(acc[r][0] * inv, acc[r][1] * inv,
                        acc[r][2] * inv, acc[r][3] * inv);
    }
}

// ======================================================================
extern "C" void kernel_launch(void* const* d_in, const int* in_sizes, int n_in,
                              void* d_out, int out_size)
{
    const float* x      = (const float*)d_in[0];
    const float* w_attn = (const float*)d_in[1];
    const float* w_proj = (const float*)d_in[2];
    float* out = (float*)d_out;

    rope_table_kernel<<<(Tseq * 32) / 256, 256>>>();

    gemm_nt<0><<<dim3(QKVN / 128, MROWS / 128), 256>>>(x, w_attn, nullptr,
                                                       MROWS, QKVN, Cdim);

    rope_kernel<<<(Bsz * Tseq * Hn * 32) / 256, 256>>>();

    attn_kernel<<<dim3(Tseq / 64, BHn), 256>>>();

    gemm_nt<1><<<dim3(Cdim / 128, MROWS / 128), 256>>>(nullptr, w_proj, out,
                                                       MROWS, Cdim, Cdim);
}

// round 8
// speedup vs baseline: 1.5585x; 1.0160x over previous
#include <cuda_runtime.h>
#include <math.h>

#define Bsz   2
#define Tseq  2048
#define Cdim  1024
#define Hn    16
#define HD    64
#define BHn   (Bsz*Hn)          // 32
#define MROWS (Bsz*Tseq)        // 4096
#define QKVN  (3*Cdim)          // 3072

// ---- scratch (static device globals; no allocation) ----
__device__ float g_qkv[(size_t)MROWS * QKVN];     // [B*T, 3C]
__device__ float g_Q[(size_t)BHn * Tseq * HD];    // [B,H,T,hd]
__device__ float g_K[(size_t)BHn * Tseq * HD];
__device__ float g_V[(size_t)BHn * Tseq * HD];
__device__ float g_att[(size_t)MROWS * Cdim];     // [B,T,C] pre-projection
__device__ float g_cos[Tseq * 32];                // rope tables [t][j]
__device__ float g_sin[Tseq * 32];

// ======================================================================
// C[M,N] = A[M,K] * B[N,K]^T  (fp32, K-major). 128x128 tile, BK=16,
// 256 threads, 8x8 microtile, register-prefetch pipeline.
// ======================================================================
template<int MODE>
__global__ void __launch_bounds__(256) gemm_nt(const float* __restrict__ Aext,
                                               const float* __restrict__ Bm,
                                               float* __restrict__ Cext,
                                               int M, int N, int K)
{
    const float* A  = (MODE == 0) ? Aext : (const float*)g_att;
    float*       Cm = (MODE == 0) ? (float*)g_qkv : Cext;

    const int BK = 16;
    __shared__ float As[BK][128];
    __shared__ float Bs[BK][128];

    const int tid = threadIdx.x;
    const int tx = tid & 15;
    const int ty = tid >> 4;
    const int rowBase = blockIdx.y * 128;
    const int colBase = blockIdx.x * 128;
    const int lr = tid >> 1;
    const int lc = (tid & 1) << 3;

    const float* Aptr = A + (size_t)(rowBase + lr) * K + lc;
    const float* Bptr = Bm + (size_t)(colBase + lr) * K + lc;

    float acc[8][8];
    #pragma unroll
    for (int i = 0; i < 8; ++i)
        #pragma unroll
        for (int j = 0; j < 8; ++j) acc[i][j] = 0.f;

    float4 pa0 = *reinterpret_cast<const float4*>(Aptr);
    float4 pa1 = *reinterpret_cast<const float4*>(Aptr + 4);
    float4 pb0 = *reinterpret_cast<const float4*>(Bptr);
    float4 pb1 = *reinterpret_cast<const float4*>(Bptr + 4);

    for (int k0 = 0; k0 < K; k0 += BK) {
        As[lc+0][lr]=pa0.x; As[lc+1][lr]=pa0.y; As[lc+2][lr]=pa0.z; As[lc+3][lr]=pa0.w;
        As[lc+4][lr]=pa1.x; As[lc+5][lr]=pa1.y; As[lc+6][lr]=pa1.z; As[lc+7][lr]=pa1.w;
        Bs[lc+0][lr]=pb0.x; Bs[lc+1][lr]=pb0.y; Bs[lc+2][lr]=pb0.z; Bs[lc+3][lr]=pb0.w;
        Bs[lc+4][lr]=pb1.x; Bs[lc+5][lr]=pb1.y; Bs[lc+6][lr]=pb1.z; Bs[lc+7][lr]=pb1.w;
        __syncthreads();

        if (k0 + BK < K) {
            pa0 = *reinterpret_cast<const float4*>(Aptr + k0 + BK);
            pa1 = *reinterpret_cast<const float4*>(Aptr + k0 + BK + 4);
            pb0 = *reinterpret_cast<const float4*>(Bptr + k0 + BK);
            pb1 = *reinterpret_cast<const float4*>(Bptr + k0 + BK + 4);
        }

        #pragma unroll
        for (int kk = 0; kk < BK; ++kk) {
            float4 a0 = *reinterpret_cast<const float4*>(&As[kk][ty << 3]);
            float4 a1 = *reinterpret_cast<const float4*>(&As[kk][(ty << 3) + 4]);
            float4 b0 = *reinterpret_cast<const float4*>(&Bs[kk][tx << 3]);
            float4 b1 = *reinterpret_cast<const float4*>(&Bs[kk][(tx << 3) + 4]);
            float ar[8] = {a0.x,a0.y,a0.z,a0.w,a1.x,a1.y,a1.z,a1.w};
            float br[8] = {b0.x,b0.y,b0.z,b0.w,b1.x,b1.y,b1.z,b1.w};
            #pragma unroll
            for (int i = 0; i < 8; ++i)
                #pragma unroll
                for (int j = 0; j < 8; ++j)
                    acc[i][j] = fmaf(ar[i], br[j], acc[i][j]);
        }
        __syncthreads();
    }

    #pragma unroll
    for (int i = 0; i < 8; ++i) {
        float* crow = Cm + (size_t)(rowBase + (ty << 3) + i) * N + colBase + (tx << 3);
        *reinterpret_cast<float4*>(crow) =
            make_float4(acc[i][0], acc[i][1], acc[i][2], acc[i][3]);
        *reinterpret_cast<float4*>(crow + 4) =
            make_float4(acc[i][4], acc[i][5], acc[i][6], acc[i][7]);
    }
}

// ======================================================================
// RoPE tables (double precision, tiny)
// ======================================================================
__global__ void rope_table_kernel()
{
    int idx = blockIdx.x * blockDim.x + threadIdx.x;
    int j = idx & 31;
    int t = idx >> 5;
    double invf = exp(-(double)j * (9.210340371976184 / 32.0));
    double sd, cd;
    sincos((double)t * invf, &sd, &cd);
    g_cos[idx] = (float)cd;
    g_sin[idx] = (float)sd;
}

// ======================================================================
// RoPE + QKV split/transpose
// ======================================================================
__global__ void rope_kernel()
{
    int idx = blockIdx.x * blockDim.x + threadIdx.x;
    int j = idx & 31;
    int h = (idx >> 5) & (Hn - 1);
    int t = (idx >> 9) & (Tseq - 1);
    int b = idx >> 20;

    size_t base = (size_t)(b * Tseq + t) * QKVN;
    int qo = h * HD + j;

    float c = g_cos[(t << 5) + j];
    float s = g_sin[(t << 5) + j];

    size_t o = ((size_t)(b * Hn + h) * Tseq + t) * HD + j;

    float q0 = g_qkv[base + qo];
    float q1 = g_qkv[base + qo + 32];
    g_Q[o]      = q0 * c - q1 * s;
    g_Q[o + 32] = q1 * c + q0 * s;

    float k0 = g_qkv[base + Cdim + qo];
    float k1 = g_qkv[base + Cdim + qo + 32];
    g_K[o]      = k0 * c - k1 * s;
    g_K[o + 32] = k1 * c + k0 * s;

    g_V[o]      = g_qkv[base + 2 * Cdim + qo];
    g_V[o + 32] = g_qkv[base + 2 * Cdim + qo + 32];
}

// ======================================================================
// Flash attention, fp32, causal. 64 threads/block, Br=Bc=64.
// Thread (ty=tid>>3, tx=tid&7) owns an 8x8 patch. 8x8 microtile GEMMs
// for QK and PV: 64B LDS per 64 FMA (1 B/FMA). Chunk swizzle
// p = c ^ (c>>3) on the j/e dimension for conflict-free reads.
// smem = 3 x 16KB = 48KB. Softmax stats in regs, 8-lane shfl butterfly.
// ======================================================================
__global__ void __launch_bounds__(64) attn_kernel()
{
    __shared__ float qs[64 * 64];    // Q^T [d][i]
    __shared__ float ksb[64 * 64];   // K^T [d][j] (QK) / P [i][j] (PV)
    __shared__ float vs[64 * 64];    // V [j][e], e-chunks swizzled

    const int qtile = gridDim.x - 1 - blockIdx.x;   // longest first
    const int bh    = blockIdx.y;
    const int tid   = threadIdx.x;
    const int tx = tid & 7;
    const int ty = tid >> 3;

    // physical chunk indices (swizzle p = c ^ (c>>3)) for chunks 2tx, 2tx+1
    const int p0 = (2 * tx) ^ ((2 * tx) >> 3);
    const int p1 = (2 * tx + 1) ^ ((2 * tx + 1) >> 3);

    const float* Qb = g_Q + ((size_t)bh * Tseq + qtile * 64) * HD;
    const float* Kb = g_K + (size_t)bh * Tseq * HD;
    const float* Vb = g_V + (size_t)bh * Tseq * HD;

    // ---- load Q tile transposed into qs[d][i], fold 1/8 scale ----
    {
        const int d4 = tid >> 5;      // 0..1
        const int i  = tid & 31;
        #pragma unroll
        for (int ii = 0; ii < 2; ++ii) {
            #pragma unroll
            for (int dd = 0; dd < 8; ++dd) {
                int row = i + 32 * ii;
                int d0  = (d4 + dd * 2) * 4;
                float4 v = *reinterpret_cast<const float4*>(Qb + row * HD + d0);
                qs[(d0 + 0) * 64 + row] = v.x * 0.125f;
                qs[(d0 + 1) * 64 + row] = v.y * 0.125f;
                qs[(d0 + 2) * 64 + row] = v.z * 0.125f;
                qs[(d0 + 3) * 64 + row] = v.w * 0.125f;
            }
        }
    }

    float acc[8][8];
    #pragma unroll
    for (int r = 0; r < 8; ++r)
        #pragma unroll
        for (int e = 0; e < 8; ++e) acc[r][e] = 0.f;
    float m[8], l[8];
    #pragma unroll
    for (int r = 0; r < 8; ++r) { m[r] = -1e30f; l[r] = 0.f; }

    for (int t0 = 0; t0 <= qtile; ++t0) {
        const int kbase = t0 * 64;

        __syncthreads();   // prior PV (and qs store on iter 0) complete
        // ---- K^T -> ksb[d][jphys], j-swizzled; lane=row -> no conflicts ----
        {
            const int d4 = tid >> 5;
            const int jl = tid & 31;
            #pragma unroll
            for (int ii = 0; ii < 2; ++ii) {
                int j  = jl + 32 * ii;
                int jp = j ^ ((j >> 5) << 2);   // chunk swizzle in j units
                #pragma unroll
                for (int dd = 0; dd < 8; ++dd) {
                    int d0 = (d4 + dd * 2) * 4;
                    float4 v = *reinterpret_cast<const float4*>(
                        Kb + (size_t)(kbase + j) * HD + d0);
                    ksb[(d0 + 0) * 64 + jp] = v.x;
                    ksb[(d0 + 1) * 64 + jp] = v.y;
                    ksb[(d0 + 2) * 64 + jp] = v.z;
                    ksb[(d0 + 3) * 64 + jp] = v.w;
                }
            }
        }
        // ---- V -> vs[j][e], e-chunks swizzled (64-thread geometry:
        //      r0 = tid>>4 in 0..3, rows r0*16 + jj cover all 64) ----
        {
            const int f  = tid & 15;
            const int r0 = tid >> 4;          // 0..3
            const int pf = f ^ (f >> 3);
            #pragma unroll
            for (int jj = 0; jj < 16; ++jj) {
                int row = r0 * 16 + jj;
                float4 v = *reinterpret_cast<const float4*>(
                    Vb + (size_t)(kbase + row) * HD + 4 * f);
                *reinterpret_cast<float4*>(vs + row * 64 + 4 * pf) = v;
            }
        }
        __syncthreads();

        // ---- QK 8x8 microtile over d ----
        float S[8][8];
        #pragma unroll
        for (int r = 0; r < 8; ++r)
            #pragma unroll
            for (int c = 0; c < 8; ++c) S[r][c] = 0.f;

        #pragma unroll 4
        for (int d = 0; d < 64; ++d) {
            float4 a0 = *reinterpret_cast<const float4*>(qs + d * 64 + 8 * ty);
            float4 a1 = *reinterpret_cast<const float4*>(qs + d * 64 + 8 * ty + 4);
            float4 b0 = *reinterpret_cast<const float4*>(ksb + d * 64 + 4 * p0);
            float4 b1 = *reinterpret_cast<const float4*>(ksb + d * 64 + 4 * p1);
            float ar[8] = {a0.x,a0.y,a0.z,a0.w,a1.x,a1.y,a1.z,a1.w};
            float br[8] = {b0.x,b0.y,b0.z,b0.w,b1.x,b1.y,b1.z,b1.w};
            #pragma unroll
            for (int r = 0; r < 8; ++r)
                #pragma unroll
                for (int c = 0; c < 8; ++c)
                    S[r][c] = fmaf(ar[r], br[c], S[r][c]);
        }

        // ---- causal mask on diagonal tile ----
        if (t0 == qtile) {
            #pragma unroll
            for (int r = 0; r < 8; ++r)
                #pragma unroll
                for (int c = 0; c < 8; ++c)
                    if (8 * tx + c > 8 * ty + r) S[r][c] = -1e30f;
        }

        // ---- online softmax (8-lane butterfly over tx group) ----
        #pragma unroll
        for (int r = 0; r < 8; ++r) {
            float vmax = S[r][0];
            #pragma unroll
            for (int c = 1; c < 8; ++c) vmax = fmaxf(vmax, S[r][c]);
            #pragma unroll
            for (int mk = 1; mk < 8; mk <<= 1)
                vmax = fmaxf(vmax, __shfl_xor_sync(0xffffffffu, vmax, mk));
            float mn = fmaxf(m[r], vmax);
            float corr = __expf(m[r] - mn);
            m[r] = mn;
            l[r] *= corr;
            #pragma unroll
            for (int e = 0; e < 8; ++e) acc[r][e] *= corr;
            float lsum = 0.f;
            #pragma unroll
            for (int c = 0; c < 8; ++c) {
                S[r][c] = __expf(S[r][c] - mn);
                lsum += S[r][c];
            }
            #pragma unroll
            for (int mk = 1; mk < 8; mk <<= 1)
                lsum += __shfl_xor_sync(0xffffffffu, lsum, mk);
            l[r] += lsum;
        }

        // ---- P -> ksb as [i][j], j-chunks swizzled ----
        __syncthreads();
        #pragma unroll
        for (int r = 0; r < 8; ++r) {
            float* prow = ksb + (8 * ty + r) * 64;
            *reinterpret_cast<float4*>(prow + 4 * p0) =
                make_float4(S[r][0], S[r][1], S[r][2], S[r][3]);
            *reinterpret_cast<float4*>(prow + 4 * p1) =
                make_float4(S[r][4], S[r][5], S[r][6], S[r][7]);
        }
        __syncthreads();

        // ---- PV 8x8 microtile over j (4 at a time) ----
        #pragma unroll 2
        for (int j4 = 0; j4 < 16; ++j4) {
            const int pj = j4 ^ (j4 >> 3);
            float P_[8][4];
            #pragma unroll
            for (int r = 0; r < 8; ++r) {
                float4 pv = *reinterpret_cast<const float4*>(
                    ksb + (8 * ty + r) * 64 + 4 * pj);
                P_[r][0] = pv.x; P_[r][1] = pv.y; P_[r][2] = pv.z; P_[r][3] = pv.w;
            }
            #pragma unroll
            for (int jj = 0; jj < 4; ++jj) {
                int j = 4 * j4 + jj;
                float4 va = *reinterpret_cast<const float4*>(vs + j * 64 + 4 * p0);
                float4 vb = *reinterpret_cast<const float4*>(vs + j * 64 + 4 * p1);
                float vr[8] = {va.x,va.y,va.z,va.w,vb.x,vb.y,vb.z,vb.w};
                #pragma unroll
                for (int r = 0; r < 8; ++r) {
                    float p = P_[r][jj];
                    #pragma unroll
                    for (int e = 0; e < 8; ++e)
                        acc[r][e] = fmaf(p, vr[e], acc[r][e]);
                }
            }
        }
    }

    // ---- output ----
    const int b = bh >> 4;
    const int h = bh & 15;
    #pragma unroll
    for (int r = 0; r < 8; ++r) {
        float inv = 1.f / l[r];
        int qi = qtile * 64 + 8 * ty + r;
        float* op = g_att + (size_t)(b * Tseq + qi) * Cdim + h * HD + 8 * tx;
        *reinterpret_cast<float4*>(op) =
            make_float4(acc[r][0] * inv, acc[r][1] * inv,
                        acc[r][2] * inv, acc[r][3] * inv);
        *reinterpret_cast<float4*>(op + 4) =
            make_float4(acc[r][4] * inv, acc[r][5] * inv,
                        acc[r][6] * inv, acc[r][7] * inv);
    }
}

// ======================================================================
extern "C" void kernel_launch(void* const* d_in, const int* in_sizes, int n_in,
                              void* d_out, int out_size)
{
    const float* x      = (const float*)d_in[0];
    const float* w_attn = (const float*)d_in[1];
    const float* w_proj = (const float*)d_in[2];
    float* out = (float*)d_out;

    rope_table_kernel<<<(Tseq * 32) / 256, 256>>>();

    gemm_nt<0><<<dim3(QKVN / 128, MROWS / 128), 256>>>(x, w_attn, nullptr,
                                                       MROWS, QKVN, Cdim);

    rope_kernel<<<(Bsz * Tseq * Hn * 32) / 256, 256>>>();

    attn_kernel<<<dim3(Tseq / 64, BHn), 64>>>();

    gemm_nt<1><<<dim3(Cdim / 128, MROWS / 128), 256>>>(nullptr, w_proj, out,
                                                       MROWS, Cdim, Cdim);
}

// round 11
// speedup vs baseline: 1.9227x; 1.2337x over previous
#include <cuda_runtime.h>
#include <cuda_bf16.h>
#include <math.h>
#include <stdint.h>

#define Bsz   2
#define Tseq  2048
#define Cdim  1024
#define Hn    16
#define HD    64
#define BHn   (Bsz*Hn)          // 32
#define MROWS (Bsz*Tseq)        // 4096
#define QKVN  (3*Cdim)          // 3072

// ---- scratch (static device globals; no allocation) ----
__device__ float g_qkv[(size_t)MROWS * QKVN];     // [B*T, 3C]
__device__ float g_Q[(size_t)BHn * Tseq * HD];    // [B,H,T,hd]
__device__ float g_K[(size_t)BHn * Tseq * HD];
__device__ float g_V[(size_t)BHn * Tseq * HD];
__device__ float g_att[(size_t)MROWS * Cdim];     // [B,T,C] pre-projection
__device__ float g_cos[Tseq * 32];                // rope tables [t][j]
__device__ float g_sin[Tseq * 32];

// ======================================================================
// bf16 split helper: x -> (hi, lo) packed 2-at-a-time into .b32
// ======================================================================
__device__ __forceinline__ void cvt2(float x, float y, uint32_t& hi, uint32_t& lo)
{
    __nv_bfloat16 hx = __float2bfloat16_rn(x);
    __nv_bfloat16 hy = __float2bfloat16_rn(y);
    float rx = x - __bfloat162float(hx);
    float ry = y - __bfloat162float(hy);
    __nv_bfloat16 lx = __float2bfloat16_rn(rx);
    __nv_bfloat16 ly = __float2bfloat16_rn(ry);
    hi = (uint32_t)__bfloat16_as_ushort(hx) | ((uint32_t)__bfloat16_as_ushort(hy) << 16);
    lo = (uint32_t)__bfloat16_as_ushort(lx) | ((uint32_t)__bfloat16_as_ushort(ly) << 16);
}

__device__ __forceinline__ void mma_bf16(float* d, const uint32_t* a, const uint32_t* b)
{
    asm volatile(
        "mma.sync.aligned.m16n8k16.row.col.f32.bf16.bf16.f32 "
        "{%0,%1,%2,%3}, {%4,%5,%6,%7}, {%8,%9}, {%0,%1,%2,%3};"
        : "+f"(d[0]), "+f"(d[1]), "+f"(d[2]), "+f"(d[3])
        : "r"(a[0]), "r"(a[1]), "r"(a[2]), "r"(a[3]), "r"(b[0]), "r"(b[1]));
}

// ======================================================================
// Tensor-core GEMM via mma.sync bf16, 3-product hi/lo split (exact to
// ~1e-5): C[M,N] = A[M,K] * B[N,K]^T, fp32 in/out.
// CTA: 128x64 C tile, 256 threads (8 warps of 32x32), K chunks of 32.
// smem rows padded to 36 words -> conflict-free fragment LDS.
// MODE 0: A = x (param), C = g_qkv.   MODE 1: A = g_att, C = out.
// ======================================================================
#define PADW 36    // words per smem row (72 bf16: 32 hi | 32 lo | 8 pad)

template<int MODE>
__global__ void __launch_bounds__(256, 2) gemm_bf(const float* __restrict__ Aext,
                                                  const float* __restrict__ Bm,
                                                  float* __restrict__ Cext,
                                                  int M, int N, int K)
{
    const float* A  = (MODE == 0) ? Aext : (const float*)g_att;
    float*       Cm = (MODE == 0) ? (float*)g_qkv : Cext;

    __shared__ uint32_t As[128 * PADW];   // 18432 B
    __shared__ uint32_t Bs[64 * PADW];    //  9216 B

    const int tid  = threadIdx.x;
    const int wid  = tid >> 5;
    const int lane = tid & 31;
    const int g    = lane >> 2;      // fragment group row
    const int i4   = lane & 3;       // fragment k pair
    const int wm   = wid & 3;        // warp row (32 rows each)
    const int wn   = wid >> 2;       // warp col (32 cols each)

    const int rowBase = blockIdx.y * 128;
    const int colBase = blockIdx.x * 64;

    // loader geometry
    const int ar = tid >> 1, ah = tid & 1;          // A: row, 16-col half
    const int br = tid >> 2, bq = tid & 3;          // B: row, 8-col quarter
    const float* Aptr = A  + (size_t)(rowBase + ar) * K + ah * 16;
    const float* Bptr = Bm + (size_t)(colBase + br) * K + bq * 8;

    float acc[2][4][4];
    #pragma unroll
    for (int mi = 0; mi < 2; ++mi)
        #pragma unroll
        for (int ni = 0; ni < 4; ++ni)
            #pragma unroll
            for (int q = 0; q < 4; ++q) acc[mi][ni][q] = 0.f;

    // prefetch chunk 0
    float4 pa[4], pb[2];
    #pragma unroll
    for (int q = 0; q < 4; ++q)
        pa[q] = *reinterpret_cast<const float4*>(Aptr + q * 4);
    #pragma unroll
    for (int q = 0; q < 2; ++q)
        pb[q] = *reinterpret_cast<const float4*>(Bptr + q * 4);

    const int NCHUNK = K / 32;
    for (int c = 0; c < NCHUNK; ++c) {
        // ---- convert prefetched regs into smem hi|lo ----
        {
            uint32_t* aw = As + ar * PADW + ah * 8;
            #pragma unroll
            for (int q = 0; q < 4; ++q) {
                uint32_t h0, l0, h1, l1;
                cvt2(pa[q].x, pa[q].y, h0, l0);
                cvt2(pa[q].z, pa[q].w, h1, l1);
                aw[q * 2]          = h0;
                aw[q * 2 + 1]      = h1;
                aw[q * 2 + 16]     = l0;
                aw[q * 2 + 17]     = l1;
            }
            uint32_t* bw = Bs + br * PADW + bq * 4;
            #pragma unroll
            for (int q = 0; q < 2; ++q) {
                uint32_t h0, l0, h1, l1;
                cvt2(pb[q].x, pb[q].y, h0, l0);
                cvt2(pb[q].z, pb[q].w, h1, l1);
                bw[q * 2]          = h0;
                bw[q * 2 + 1]      = h1;
                bw[q * 2 + 16]     = l0;
                bw[q * 2 + 17]     = l1;
            }
        }
        __syncthreads();

        if (c + 1 < NCHUNK) {   // prefetch next chunk (flies during MMA)
            #pragma unroll
            for (int q = 0; q < 4; ++q)
                pa[q] = *reinterpret_cast<const float4*>(Aptr + (c + 1) * 32 + q * 4);
            #pragma unroll
            for (int q = 0; q < 2; ++q)
                pb[q] = *reinterpret_cast<const float4*>(Bptr + (c + 1) * 32 + q * 4);
        }

        // ---- 3 products: (Ahi,Bhi), (Ahi,Blo), (Alo,Bhi); 2 k16 steps each
        #pragma unroll
        for (int p = 0; p < 3; ++p) {
            const int aoff = (p == 2) ? 16 : 0;
            const int boff = (p == 1) ? 16 : 0;
            #pragma unroll
            for (int ks = 0; ks < 2; ++ks) {
                const int kwA = aoff + ks * 8 + i4;
                const int kwB = boff + ks * 8 + i4;
                uint32_t a[2][4], b[4][2];
                #pragma unroll
                for (int mi = 0; mi < 2; ++mi) {
                    const uint32_t* base = As + (wm * 32 + mi * 16 + g) * PADW + kwA;
                    a[mi][0] = base[0];
                    a[mi][1] = base[8 * PADW];
                    a[mi][2] = base[4];
                    a[mi][3] = base[8 * PADW + 4];
                }
                #pragma unroll
                for (int ni = 0; ni < 4; ++ni) {
                    const uint32_t* base = Bs + (wn * 32 + ni * 8 + g) * PADW + kwB;
                    b[ni][0] = base[0];
                    b[ni][1] = base[4];
                }
                #pragma unroll
                for (int mi = 0; mi < 2; ++mi)
                    #pragma unroll
                    for (int ni = 0; ni < 4; ++ni)
                        mma_bf16(acc[mi][ni], a[mi], b[ni]);
            }
        }
        __syncthreads();
    }

    // ---- epilogue: fragment layout -> global ----
    #pragma unroll
    for (int mi = 0; mi < 2; ++mi) {
        #pragma unroll
        for (int ni = 0; ni < 4; ++ni) {
            int row = rowBase + wm * 32 + mi * 16 + g;
            int col = colBase + wn * 32 + ni * 8 + 2 * i4;
            float* c0 = Cm + (size_t)row * N + col;
            c0[0] = acc[mi][ni][0];
            c0[1] = acc[mi][ni][1];
            float* c2 = c0 + 8 * N;
            c2[0] = acc[mi][ni][2];
            c2[1] = acc[mi][ni][3];
        }
    }
}

// ======================================================================
// RoPE tables (double precision, tiny)
// ======================================================================
__global__ void rope_table_kernel()
{
    int idx = blockIdx.x * blockDim.x + threadIdx.x;
    int j = idx & 31;
    int t = idx >> 5;
    double invf = exp(-(double)j * (9.210340371976184 / 32.0));
    double sd, cd;
    sincos((double)t * invf, &sd, &cd);
    g_cos[idx] = (float)cd;
    g_sin[idx] = (float)sd;
}

// ======================================================================
// RoPE + QKV split/transpose
// ======================================================================
__global__ void rope_kernel()
{
    int idx = blockIdx.x * blockDim.x + threadIdx.x;
    int j = idx & 31;
    int h = (idx >> 5) & (Hn - 1);
    int t = (idx >> 9) & (Tseq - 1);
    int b = idx >> 20;

    size_t base = (size_t)(b * Tseq + t) * QKVN;
    int qo = h * HD + j;

    float c = g_cos[(t << 5) + j];
    float s = g_sin[(t << 5) + j];

    size_t o = ((size_t)(b * Hn + h) * Tseq + t) * HD + j;

    float q0 = g_qkv[base + qo];
    float q1 = g_qkv[base + qo + 32];
    g_Q[o]      = q0 * c - q1 * s;
    g_Q[o + 32] = q1 * c + q0 * s;

    float k0 = g_qkv[base + Cdim + qo];
    float k1 = g_qkv[base + Cdim + qo + 32];
    g_K[o]      = k0 * c - k1 * s;
    g_K[o + 32] = k1 * c + k0 * s;

    g_V[o]      = g_qkv[base + 2 * Cdim + qo];
    g_V[o + 32] = g_qkv[base + 2 * Cdim + qo + 32];
}

// ======================================================================
// Flash attention, fp32, causal (unchanged from R8: 718us, correct).
// ======================================================================
__global__ void __launch_bounds__(64) attn_kernel()
{
    __shared__ float qs[64 * 64];    // Q^T [d][i]
    __shared__ float ksb[64 * 64];   // K^T [d][j] (QK) / P [i][j] (PV)
    __shared__ float vs[64 * 64];    // V [j][e], e-chunks swizzled

    const int qtile = gridDim.x - 1 - blockIdx.x;
    const int bh    = blockIdx.y;
    const int tid   = threadIdx.x;
    const int tx = tid & 7;
    const int ty = tid >> 3;

    const int p0 = (2 * tx) ^ ((2 * tx) >> 3);
    const int p1 = (2 * tx + 1) ^ ((2 * tx + 1) >> 3);

    const float* Qb = g_Q + ((size_t)bh * Tseq + qtile * 64) * HD;
    const float* Kb = g_K + (size_t)bh * Tseq * HD;
    const float* Vb = g_V + (size_t)bh * Tseq * HD;

    {
        const int d4 = tid >> 5;
        const int i  = tid & 31;
        #pragma unroll
        for (int ii = 0; ii < 2; ++ii) {
            #pragma unroll
            for (int dd = 0; dd < 8; ++dd) {
                int row = i + 32 * ii;
                int d0  = (d4 + dd * 2) * 4;
                float4 v = *reinterpret_cast<const float4*>(Qb + row * HD + d0);
                qs[(d0 + 0) * 64 + row] = v.x * 0.125f;
                qs[(d0 + 1) * 64 + row] = v.y * 0.125f;
                qs[(d0 + 2) * 64 + row] = v.z * 0.125f;
                qs[(d0 + 3) * 64 + row] = v.w * 0.125f;
            }
        }
    }

    float acc[8][8];
    #pragma unroll
    for (int r = 0; r < 8; ++r)
        #pragma unroll
        for (int e = 0; e < 8; ++e) acc[r][e] = 0.f;
    float m[8], l[8];
    #pragma unroll
    for (int r = 0; r < 8; ++r) { m[r] = -1e30f; l[r] = 0.f; }

    for (int t0 = 0; t0 <= qtile; ++t0) {
        const int kbase = t0 * 64;

        __syncthreads();
        {
            const int d4 = tid >> 5;
            const int jl = tid & 31;
            #pragma unroll
            for (int ii = 0; ii < 2; ++ii) {
                int j  = jl + 32 * ii;
                int jp = j ^ ((j >> 5) << 2);
                #pragma unroll
                for (int dd = 0; dd < 8; ++dd) {
                    int d0 = (d4 + dd * 2) * 4;
                    float4 v = *reinterpret_cast<const float4*>(
                        Kb + (size_t)(kbase + j) * HD + d0);
                    ksb[(d0 + 0) * 64 + jp] = v.x;
                    ksb[(d0 + 1) * 64 + jp] = v.y;
                    ksb[(d0 + 2) * 64 + jp] = v.z;
                    ksb[(d0 + 3) * 64 + jp] = v.w;
                }
            }
        }
        {
            const int f  = tid & 15;
            const int r0 = tid >> 4;
            const int pf = f ^ (f >> 3);
            #pragma unroll
            for (int jj = 0; jj < 16; ++jj) {
                int row = r0 * 16 + jj;
                float4 v = *reinterpret_cast<const float4*>(
                    Vb + (size_t)(kbase + row) * HD + 4 * f);
                *reinterpret_cast<float4*>(vs + row * 64 + 4 * pf) = v;
            }
        }
        __syncthreads();

        float S[8][8];
        #pragma unroll
        for (int r = 0; r < 8; ++r)
            #pragma unroll
            for (int c = 0; c < 8; ++c) S[r][c] = 0.f;

        #pragma unroll 4
        for (int d = 0; d < 64; ++d) {
            float4 a0 = *reinterpret_cast<const float4*>(qs + d * 64 + 8 * ty);
            float4 a1 = *reinterpret_cast<const float4*>(qs + d * 64 + 8 * ty + 4);
            float4 b0 = *reinterpret_cast<const float4*>(ksb + d * 64 + 4 * p0);
            float4 b1 = *reinterpret_cast<const float4*>(ksb + d * 64 + 4 * p1);
            float ar[8] = {a0.x,a0.y,a0.z,a0.w,a1.x,a1.y,a1.z,a1.w};
            float br[8] = {b0.x,b0.y,b0.z,b0.w,b1.x,b1.y,b1.z,b1.w};
            #pragma unroll
            for (int r = 0; r < 8; ++r)
                #pragma unroll
                for (int c = 0; c < 8; ++c)
                    S[r][c] = fmaf(ar[r], br[c], S[r][c]);
        }

        if (t0 == qtile) {
            #pragma unroll
            for (int r = 0; r < 8; ++r)
                #pragma unroll
                for (int c = 0; c < 8; ++c)
                    if (8 * tx + c > 8 * ty + r) S[r][c] = -1e30f;
        }

        #pragma unroll
        for (int r = 0; r < 8; ++r) {
            float vmax = S[r][0];
            #pragma unroll
            for (int c = 1; c < 8; ++c) vmax = fmaxf(vmax, S[r][c]);
            #pragma unroll
            for (int mk = 1; mk < 8; mk <<= 1)
                vmax = fmaxf(vmax, __shfl_xor_sync(0xffffffffu, vmax, mk));
            float mn = fmaxf(m[r], vmax);
            float corr = __expf(m[r] - mn);
            m[r] = mn;
            l[r] *= corr;
            #pragma unroll
            for (int e = 0; e < 8; ++e) acc[r][e] *= corr;
            float lsum = 0.f;
            #pragma unroll
            for (int c = 0; c < 8; ++c) {
                S[r][c] = __expf(S[r][c] - mn);
                lsum += S[r][c];
            }
            #pragma unroll
            for (int mk = 1; mk < 8; mk <<= 1)
                lsum += __shfl_xor_sync(0xffffffffu, lsum, mk);
            l[r] += lsum;
        }

        __syncthreads();
        #pragma unroll
        for (int r = 0; r < 8; ++r) {
            float* prow = ksb + (8 * ty + r) * 64;
            *reinterpret_cast<float4*>(prow + 4 * p0) =
                make_float4(S[r][0], S[r][1], S[r][2], S[r][3]);
            *reinterpret_cast<float4*>(prow + 4 * p1) =
                make_float4(S[r][4], S[r][5], S[r][6], S[r][7]);
        }
        __syncthreads();

        #pragma unroll 2
        for (int j4 = 0; j4 < 16; ++j4) {
            const int pj = j4 ^ (j4 >> 3);
            float P_[8][4];
            #pragma unroll
            for (int r = 0; r < 8; ++r) {
                float4 pv = *reinterpret_cast<const float4*>(
                    ksb + (8 * ty + r) * 64 + 4 * pj);
                P_[r][0] = pv.x; P_[r][1] = pv.y; P_[r][2] = pv.z; P_[r][3] = pv.w;
            }
            #pragma unroll
            for (int jj = 0; jj < 4; ++jj) {
                int j = 4 * j4 + jj;
                float4 va = *reinterpret_cast<const float4*>(vs + j * 64 + 4 * p0);
                float4 vb = *reinterpret_cast<const float4*>(vs + j * 64 + 4 * p1);
                float vr[8] = {va.x,va.y,va.z,va.w,vb.x,vb.y,vb.z,vb.w};
                #pragma unroll
                for (int r = 0; r < 8; ++r) {
                    float p = P_[r][jj];
                    #pragma unroll
                    for (int e = 0; e < 8; ++e)
                        acc[r][e] = fmaf(p, vr[e], acc[r][e]);
                }
            }
        }
    }

    const int b = bh >> 4;
    const int h = bh & 15;
    #pragma unroll
    for (int r = 0; r < 8; ++r) {
        float inv = 1.f / l[r];
        int qi = qtile * 64 + 8 * ty + r;
        float* op = g_att + (size_t)(b * Tseq + qi) * Cdim + h * HD + 8 * tx;
        *reinterpret_cast<float4*>(op) =
            make_float4(acc[r][0] * inv, acc[r][1] * inv,
                        acc[r][2] * inv, acc[r][3] * inv);
        *reinterpret_cast<float4*>(op + 4) =
            make_float4(acc[r][4] * inv, acc[r][5] * inv,
                        acc[r][6] * inv, acc[r][7] * inv);
    }
}

// ======================================================================
extern "C" void kernel_launch(void* const* d_in, const int* in_sizes, int n_in,
                              void* d_out, int out_size)
{
    const float* x      = (const float*)d_in[0];
    const float* w_attn = (const float*)d_in[1];
    const float* w_proj = (const float*)d_in[2];
    float* out = (float*)d_out;

    rope_table_kernel<<<(Tseq * 32) / 256, 256>>>();

    // 1) QKV = x @ w_attn^T -> g_qkv  (mma.sync bf16, 3x split)
    gemm_bf<0><<<dim3(QKVN / 64, MROWS / 128), 256>>>(x, w_attn, nullptr,
                                                      MROWS, QKVN, Cdim);

    rope_kernel<<<(Bsz * Tseq * Hn * 32) / 256, 256>>>();

    attn_kernel<<<dim3(Tseq / 64, BHn), 64>>>();

    // 4) out = g_att @ w_proj^T  (mma.sync bf16, 3x split)
    gemm_bf<1><<<dim3(Cdim / 64, MROWS / 128), 256>>>(nullptr, w_proj, out,
                                                      MROWS, Cdim, Cdim);
}

// round 12
// speedup vs baseline: 2.8265x; 1.4700x over previous
#include <cuda_runtime.h>
#include <cuda_bf16.h>
#include <math.h>
#include <stdint.h>

#define Bsz   2
#define Tseq  2048
#define Cdim  1024
#define Hn    16
#define HD    64
#define BHn   (Bsz*Hn)          // 32
#define MROWS (Bsz*Tseq)        // 4096
#define QKVN  (3*Cdim)          // 3072

// ---- scratch (static device globals; no allocation) ----
__device__ float g_qkv[(size_t)MROWS * QKVN];     // [B*T, 3C]
__device__ float g_att[(size_t)MROWS * Cdim];     // [B,T,C] pre-projection
__device__ float g_cos[Tseq * 32];
__device__ float g_sin[Tseq * 32];
// bf16 hi/lo split tensors, [bh][t][hd] (Q pre-scaled by 1/8)
__device__ __nv_bfloat16 g_Qhi[(size_t)BHn * Tseq * HD];
__device__ __nv_bfloat16 g_Qlo[(size_t)BHn * Tseq * HD];
__device__ __nv_bfloat16 g_Khi[(size_t)BHn * Tseq * HD];
__device__ __nv_bfloat16 g_Klo[(size_t)BHn * Tseq * HD];
__device__ __nv_bfloat16 g_Vhi[(size_t)BHn * Tseq * HD];
__device__ __nv_bfloat16 g_Vlo[(size_t)BHn * Tseq * HD];
// V transposed: [bh][hd][t]
__device__ __nv_bfloat16 g_VThi[(size_t)BHn * HD * Tseq];
__device__ __nv_bfloat16 g_VTlo[(size_t)BHn * HD * Tseq];

// ======================================================================
// helpers
// ======================================================================
__device__ __forceinline__ void cvt2(float x, float y, uint32_t& hi, uint32_t& lo)
{
    __nv_bfloat16 hx = __float2bfloat16_rn(x);
    __nv_bfloat16 hy = __float2bfloat16_rn(y);
    float rx = x - __bfloat162float(hx);
    float ry = y - __bfloat162float(hy);
    __nv_bfloat16 lx = __float2bfloat16_rn(rx);
    __nv_bfloat16 ly = __float2bfloat16_rn(ry);
    hi = (uint32_t)__bfloat16_as_ushort(hx) | ((uint32_t)__bfloat16_as_ushort(hy) << 16);
    lo = (uint32_t)__bfloat16_as_ushort(lx) | ((uint32_t)__bfloat16_as_ushort(ly) << 16);
}

__device__ __forceinline__ void split2(float x, __nv_bfloat16& h, __nv_bfloat16& l)
{
    h = __float2bfloat16_rn(x);
    l = __float2bfloat16_rn(x - __bfloat162float(h));
}

__device__ __forceinline__ void mma_bf16(float* d, const uint32_t* a, const uint32_t* b)
{
    asm volatile(
        "mma.sync.aligned.m16n8k16.row.col.f32.bf16.bf16.f32 "
        "{%0,%1,%2,%3}, {%4,%5,%6,%7}, {%8,%9}, {%0,%1,%2,%3};"
        : "+f"(d[0]), "+f"(d[1]), "+f"(d[2]), "+f"(d[3])
        : "r"(a[0]), "r"(a[1]), "r"(a[2]), "r"(a[3]), "r"(b[0]), "r"(b[1]));
}

// ======================================================================
// Tensor-core GEMM via mma.sync bf16, 3-product hi/lo split.
// (unchanged from R11: passing, ~490us for both)
// ======================================================================
#define PADW 36

template<int MODE>
__global__ void __launch_bounds__(256, 2) gemm_bf(const float* __restrict__ Aext,
                                                  const float* __restrict__ Bm,
                                                  float* __restrict__ Cext,
                                                  int M, int N, int K)
{
    const float* A  = (MODE == 0) ? Aext : (const float*)g_att;
    float*       Cm = (MODE == 0) ? (float*)g_qkv : Cext;

    __shared__ uint32_t As[128 * PADW];
    __shared__ uint32_t Bs[64 * PADW];

    const int tid  = threadIdx.x;
    const int wid  = tid >> 5;
    const int lane = tid & 31;
    const int g    = lane >> 2;
    const int i4   = lane & 3;
    const int wm   = wid & 3;
    const int wn   = wid >> 2;

    const int rowBase = blockIdx.y * 128;
    const int colBase = blockIdx.x * 64;

    const int ar = tid >> 1, ah = tid & 1;
    const int br = tid >> 2, bq = tid & 3;
    const float* Aptr = A  + (size_t)(rowBase + ar) * K + ah * 16;
    const float* Bptr = Bm + (size_t)(colBase + br) * K + bq * 8;

    float acc[2][4][4];
    #pragma unroll
    for (int mi = 0; mi < 2; ++mi)
        #pragma unroll
        for (int ni = 0; ni < 4; ++ni)
            #pragma unroll
            for (int q = 0; q < 4; ++q) acc[mi][ni][q] = 0.f;

    float4 pa[4], pb[2];
    #pragma unroll
    for (int q = 0; q < 4; ++q)
        pa[q] = *reinterpret_cast<const float4*>(Aptr + q * 4);
    #pragma unroll
    for (int q = 0; q < 2; ++q)
        pb[q] = *reinterpret_cast<const float4*>(Bptr + q * 4);

    const int NCHUNK = K / 32;
    for (int c = 0; c < NCHUNK; ++c) {
        {
            uint32_t* aw = As + ar * PADW + ah * 8;
            #pragma unroll
            for (int q = 0; q < 4; ++q) {
                uint32_t h0, l0, h1, l1;
                cvt2(pa[q].x, pa[q].y, h0, l0);
                cvt2(pa[q].z, pa[q].w, h1, l1);
                aw[q * 2]      = h0;
                aw[q * 2 + 1]  = h1;
                aw[q * 2 + 16] = l0;
                aw[q * 2 + 17] = l1;
            }
            uint32_t* bw = Bs + br * PADW + bq * 4;
            #pragma unroll
            for (int q = 0; q < 2; ++q) {
                uint32_t h0, l0, h1, l1;
                cvt2(pb[q].x, pb[q].y, h0, l0);
                cvt2(pb[q].z, pb[q].w, h1, l1);
                bw[q * 2]      = h0;
                bw[q * 2 + 1]  = h1;
                bw[q * 2 + 16] = l0;
                bw[q * 2 + 17] = l1;
            }
        }
        __syncthreads();

        if (c + 1 < NCHUNK) {
            #pragma unroll
            for (int q = 0; q < 4; ++q)
                pa[q] = *reinterpret_cast<const float4*>(Aptr + (c + 1) * 32 + q * 4);
            #pragma unroll
            for (int q = 0; q < 2; ++q)
                pb[q] = *reinterpret_cast<const float4*>(Bptr + (c + 1) * 32 + q * 4);
        }

        #pragma unroll
        for (int p = 0; p < 3; ++p) {
            const int aoff = (p == 2) ? 16 : 0;
            const int boff = (p == 1) ? 16 : 0;
            #pragma unroll
            for (int ks = 0; ks < 2; ++ks) {
                const int kwA = aoff + ks * 8 + i4;
                const int kwB = boff + ks * 8 + i4;
                uint32_t a[2][4], b[4][2];
                #pragma unroll
                for (int mi = 0; mi < 2; ++mi) {
                    const uint32_t* base = As + (wm * 32 + mi * 16 + g) * PADW + kwA;
                    a[mi][0] = base[0];
                    a[mi][1] = base[8 * PADW];
                    a[mi][2] = base[4];
                    a[mi][3] = base[8 * PADW + 4];
                }
                #pragma unroll
                for (int ni = 0; ni < 4; ++ni) {
                    const uint32_t* base = Bs + (wn * 32 + ni * 8 + g) * PADW + kwB;
                    b[ni][0] = base[0];
                    b[ni][1] = base[4];
                }
                #pragma unroll
                for (int mi = 0; mi < 2; ++mi)
                    #pragma unroll
                    for (int ni = 0; ni < 4; ++ni)
                        mma_bf16(acc[mi][ni], a[mi], b[ni]);
            }
        }
        __syncthreads();
    }

    #pragma unroll
    for (int mi = 0; mi < 2; ++mi) {
        #pragma unroll
        for (int ni = 0; ni < 4; ++ni) {
            int row = rowBase + wm * 32 + mi * 16 + g;
            int col = colBase + wn * 32 + ni * 8 + 2 * i4;
            float* c0 = Cm + (size_t)row * N + col;
            c0[0] = acc[mi][ni][0];
            c0[1] = acc[mi][ni][1];
            float* c2 = c0 + 8 * N;
            c2[0] = acc[mi][ni][2];
            c2[1] = acc[mi][ni][3];
        }
    }
}

// ======================================================================
// RoPE tables (double precision, tiny)
// ======================================================================
__global__ void rope_table_kernel()
{
    int idx = blockIdx.x * blockDim.x + threadIdx.x;
    int j = idx & 31;
    int t = idx >> 5;
    double invf = exp(-(double)j * (9.210340371976184 / 32.0));
    double sd, cd;
    sincos((double)t * invf, &sd, &cd);
    g_cos[idx] = (float)cd;
    g_sin[idx] = (float)sd;
}

// ======================================================================
// RoPE + QKV split/transpose -> bf16 hi/lo arrays (Q pre-scaled 1/8)
// ======================================================================
__global__ void rope_kernel()
{
    int idx = blockIdx.x * blockDim.x + threadIdx.x;
    int j = idx & 31;
    int h = (idx >> 5) & (Hn - 1);
    int t = (idx >> 9) & (Tseq - 1);
    int b = idx >> 20;

    size_t base = (size_t)(b * Tseq + t) * QKVN;
    int qo = h * HD + j;

    float c = g_cos[(t << 5) + j];
    float s = g_sin[(t << 5) + j];

    size_t o = ((size_t)(b * Hn + h) * Tseq + t) * HD + j;

    float q0 = g_qkv[base + qo];
    float q1 = g_qkv[base + qo + 32];
    float qr0 = (q0 * c - q1 * s) * 0.125f;
    float qr1 = (q1 * c + q0 * s) * 0.125f;
    split2(qr0, g_Qhi[o],      g_Qlo[o]);
    split2(qr1, g_Qhi[o + 32], g_Qlo[o + 32]);

    float k0 = g_qkv[base + Cdim + qo];
    float k1 = g_qkv[base + Cdim + qo + 32];
    split2(k0 * c - k1 * s, g_Khi[o],      g_Klo[o]);
    split2(k1 * c + k0 * s, g_Khi[o + 32], g_Klo[o + 32]);

    split2(g_qkv[base + 2 * Cdim + qo],      g_Vhi[o],      g_Vlo[o]);
    split2(g_qkv[base + 2 * Cdim + qo + 32], g_Vhi[o + 32], g_Vlo[o + 32]);
}

// ======================================================================
// V transpose: [bh][t][hd] -> [bh][hd][t], tiled through smem.
// grid (Tseq/64, BHn), 128 threads.
// ======================================================================
__global__ void vtrans_kernel()
{
    __shared__ unsigned short sh[64 * 66], sl[64 * 66];
    const int tb = blockIdx.x * 64;
    const int bh = blockIdx.y;
    const int tid = threadIdx.x;
    const int wid = tid >> 5, lane = tid & 31;
    const int r = tid >> 1, hf = tid & 1;

    const uint32_t* srch = (const uint32_t*)(g_Vhi + ((size_t)bh * Tseq + tb + r) * HD) + hf * 16;
    const uint32_t* srcl = (const uint32_t*)(g_Vlo + ((size_t)bh * Tseq + tb + r) * HD) + hf * 16;
    uint32_t* dh = (uint32_t*)(sh + r * 66 + hf * 32);
    uint32_t* dl = (uint32_t*)(sl + r * 66 + hf * 32);
    #pragma unroll
    for (int u = 0; u < 16; ++u) { dh[u] = srch[u]; dl[u] = srcl[u]; }
    __syncthreads();

    #pragma unroll
    for (int it = 0; it < 16; ++it) {
        int d = it * 4 + wid;
        uint32_t vh = (uint32_t)sh[(2 * lane) * 66 + d] |
                      ((uint32_t)sh[(2 * lane + 1) * 66 + d] << 16);
        uint32_t vl = (uint32_t)sl[(2 * lane) * 66 + d] |
                      ((uint32_t)sl[(2 * lane + 1) * 66 + d] << 16);
        ((uint32_t*)(g_VThi + ((size_t)bh * HD + d) * Tseq + tb))[lane] = vh;
        ((uint32_t*)(g_VTlo + ((size_t)bh * HD + d) * Tseq + tb))[lane] = vl;
    }
}

// ======================================================================
// Flash attention via mma.sync bf16 (3-product hi/lo split), causal.
// 128 threads = 4 warps; warp owns 16 q rows; Br=Bc=64.
// K tiles natural [key][hd]; V tiles from VT [hd][key]. P stays in regs.
// ======================================================================
#define ATP 36   // words per smem row (64 bf16 = 32 words + 4 pad)

__global__ void __launch_bounds__(128) attn_kernel()
{
    __shared__ uint32_t Kh[64 * ATP], Kl[64 * ATP];
    __shared__ uint32_t Vh[64 * ATP], Vl[64 * ATP];

    const int qtile = gridDim.x - 1 - blockIdx.x;   // longest first
    const int bh    = blockIdx.y;
    const int tid   = threadIdx.x;
    const int wid   = tid >> 5;
    const int lane  = tid & 31;
    const int g     = lane >> 2;
    const int i4    = lane & 3;

    // ---- Q fragments from global (hi/lo), rows wid*16 + {g, g+8} ----
    uint32_t qh[4][4], ql[4][4];
    {
        const __nv_bfloat16* Qhp = g_Qhi + ((size_t)bh * Tseq + qtile * 64 + wid * 16) * HD;
        const __nv_bfloat16* Qlp = g_Qlo + ((size_t)bh * Tseq + qtile * 64 + wid * 16) * HD;
        #pragma unroll
        for (int kc = 0; kc < 4; ++kc) {
            int e0 = kc * 16 + 2 * i4;
            qh[kc][0] = *(const uint32_t*)(Qhp + g * HD + e0);
            qh[kc][1] = *(const uint32_t*)(Qhp + (g + 8) * HD + e0);
            qh[kc][2] = *(const uint32_t*)(Qhp + g * HD + e0 + 8);
            qh[kc][3] = *(const uint32_t*)(Qhp + (g + 8) * HD + e0 + 8);
            ql[kc][0] = *(const uint32_t*)(Qlp + g * HD + e0);
            ql[kc][1] = *(const uint32_t*)(Qlp + (g + 8) * HD + e0);
            ql[kc][2] = *(const uint32_t*)(Qlp + g * HD + e0 + 8);
            ql[kc][3] = *(const uint32_t*)(Qlp + (g + 8) * HD + e0 + 8);
        }
    }

    float acc[8][4];
    #pragma unroll
    for (int nf = 0; nf < 8; ++nf)
        #pragma unroll
        for (int q = 0; q < 4; ++q) acc[nf][q] = 0.f;
    float m0 = -1e30f, m1 = -1e30f, l0 = 0.f, l1 = 0.f;

    const int r = tid >> 1, hf = tid & 1;   // tile loader geometry

    for (int t0 = 0; t0 <= qtile; ++t0) {
        const int kbase = t0 * 64;
        __syncthreads();
        {   // load K hi/lo [key][hd] and VT hi/lo [hd][key] tiles
            const uint4* ksh = (const uint4*)(g_Khi + ((size_t)bh * Tseq + kbase + r) * HD + hf * 32);
            const uint4* ksl = (const uint4*)(g_Klo + ((size_t)bh * Tseq + kbase + r) * HD + hf * 32);
            const uint4* vsh = (const uint4*)(g_VThi + ((size_t)bh * HD + r) * Tseq + kbase + hf * 32);
            const uint4* vsl = (const uint4*)(g_VTlo + ((size_t)bh * HD + r) * Tseq + kbase + hf * 32);
            uint4* kdh = (uint4*)(Kh + r * ATP + hf * 16);
            uint4* kdl = (uint4*)(Kl + r * ATP + hf * 16);
            uint4* vdh = (uint4*)(Vh + r * ATP + hf * 16);
            uint4* vdl = (uint4*)(Vl + r * ATP + hf * 16);
            #pragma unroll
            for (int q = 0; q < 4; ++q) {
                kdh[q] = ksh[q];
                kdl[q] = ksl[q];
                vdh[q] = vsh[q];
                vdl[q] = vsl[q];
            }
        }
        __syncthreads();

        // ---- QK: S(16x64) fragments ----
        float S[8][4];
        #pragma unroll
        for (int nf = 0; nf < 8; ++nf)
            #pragma unroll
            for (int q = 0; q < 4; ++q) S[nf][q] = 0.f;

        #pragma unroll
        for (int kc = 0; kc < 4; ++kc) {
            #pragma unroll
            for (int nf = 0; nf < 8; ++nf) {
                const uint32_t* kb = Kh + (nf * 8 + g) * ATP + kc * 8 + i4;
                const uint32_t* kbl = Kl + (nf * 8 + g) * ATP + kc * 8 + i4;
                uint32_t bhF[2] = {kb[0], kb[4]};
                uint32_t blF[2] = {kbl[0], kbl[4]};
                mma_bf16(S[nf], qh[kc], bhF);
                mma_bf16(S[nf], qh[kc], blF);
                mma_bf16(S[nf], ql[kc], bhF);
            }
        }

        // ---- causal mask on diagonal tile ----
        if (t0 == qtile) {
            const int r0 = wid * 16 + g, r1 = r0 + 8;
            #pragma unroll
            for (int nf = 0; nf < 8; ++nf) {
                int c0 = nf * 8 + 2 * i4, c1 = c0 + 1;
                if (c0 > r0) S[nf][0] = -1e30f;
                if (c1 > r0) S[nf][1] = -1e30f;
                if (c0 > r1) S[nf][2] = -1e30f;
                if (c1 > r1) S[nf][3] = -1e30f;
            }
        }

        // ---- online softmax (stats replicated over the 4 i4 lanes) ----
        float t0max = -1e30f, t1max = -1e30f;
        #pragma unroll
        for (int nf = 0; nf < 8; ++nf) {
            t0max = fmaxf(t0max, fmaxf(S[nf][0], S[nf][1]));
            t1max = fmaxf(t1max, fmaxf(S[nf][2], S[nf][3]));
        }
        t0max = fmaxf(t0max, __shfl_xor_sync(0xffffffffu, t0max, 1));
        t0max = fmaxf(t0max, __shfl_xor_sync(0xffffffffu, t0max, 2));
        t1max = fmaxf(t1max, __shfl_xor_sync(0xffffffffu, t1max, 1));
        t1max = fmaxf(t1max, __shfl_xor_sync(0xffffffffu, t1max, 2));

        float mn0 = fmaxf(m0, t0max), mn1 = fmaxf(m1, t1max);
        float cr0 = __expf(m0 - mn0), cr1 = __expf(m1 - mn1);
        m0 = mn0; m1 = mn1;
        l0 *= cr0; l1 *= cr1;
        #pragma unroll
        for (int nf = 0; nf < 8; ++nf) {
            acc[nf][0] *= cr0; acc[nf][1] *= cr0;
            acc[nf][2] *= cr1; acc[nf][3] *= cr1;
        }

        float ps0 = 0.f, ps1 = 0.f;
        #pragma unroll
        for (int nf = 0; nf < 8; ++nf) {
            S[nf][0] = __expf(S[nf][0] - mn0); ps0 += S[nf][0];
            S[nf][1] = __expf(S[nf][1] - mn0); ps0 += S[nf][1];
            S[nf][2] = __expf(S[nf][2] - mn1); ps1 += S[nf][2];
            S[nf][3] = __expf(S[nf][3] - mn1); ps1 += S[nf][3];
        }
        ps0 += __shfl_xor_sync(0xffffffffu, ps0, 1);
        ps0 += __shfl_xor_sync(0xffffffffu, ps0, 2);
        ps1 += __shfl_xor_sync(0xffffffffu, ps1, 1);
        ps1 += __shfl_xor_sync(0xffffffffu, ps1, 2);
        l0 += ps0; l1 += ps1;

        // ---- PV: P (registers) x V^T tiles ----
        #pragma unroll
        for (int kc = 0; kc < 4; ++kc) {
            uint32_t pah[4], pal[4];
            cvt2(S[2 * kc][0],     S[2 * kc][1],     pah[0], pal[0]);
            cvt2(S[2 * kc][2],     S[2 * kc][3],     pah[1], pal[1]);
            cvt2(S[2 * kc + 1][0], S[2 * kc + 1][1], pah[2], pal[2]);
            cvt2(S[2 * kc + 1][2], S[2 * kc + 1][3], pah[3], pal[3]);
            #pragma unroll
            for (int onf = 0; onf < 8; ++onf) {
                const uint32_t* vb = Vh + (onf * 8 + g) * ATP + kc * 8 + i4;
                const uint32_t* vbl = Vl + (onf * 8 + g) * ATP + kc * 8 + i4;
                uint32_t bhF[2] = {vb[0], vb[4]};
                uint32_t blF[2] = {vbl[0], vbl[4]};
                mma_bf16(acc[onf], pah, bhF);
                mma_bf16(acc[onf], pah, blF);
                mma_bf16(acc[onf], pal, bhF);
            }
        }
    }

    // ---- output ----
    const float inv0 = 1.f / l0, inv1 = 1.f / l1;
    const int b = bh >> 4;
    const int h = bh & 15;
    const int row0 = qtile * 64 + wid * 16 + g;
    #pragma unroll
    for (int onf = 0; onf < 8; ++onf) {
        int col = h * HD + onf * 8 + 2 * i4;
        float* o0 = g_att + (size_t)(b * Tseq + row0) * Cdim + col;
        o0[0] = acc[onf][0] * inv0;
        o0[1] = acc[onf][1] * inv0;
        float* o1 = g_att + (size_t)(b * Tseq + row0 + 8) * Cdim + col;
        o1[0] = acc[onf][2] * inv1;
        o1[1] = acc[onf][3] * inv1;
    }
}

// ======================================================================
extern "C" void kernel_launch(void* const* d_in, const int* in_sizes, int n_in,
                              void* d_out, int out_size)
{
    const float* x      = (const float*)d_in[0];
    const float* w_attn = (const float*)d_in[1];
    const float* w_proj = (const float*)d_in[2];
    float* out = (float*)d_out;

    rope_table_kernel<<<(Tseq * 32) / 256, 256>>>();

    gemm_bf<0><<<dim3(QKVN / 64, MROWS / 128), 256>>>(x, w_attn, nullptr,
                                                      MROWS, QKVN, Cdim);

    rope_kernel<<<(Bsz * Tseq * Hn * 32) / 256, 256>>>();

    vtrans_kernel<<<dim3(Tseq / 64, BHn), 128>>>();

    attn_kernel<<<dim3(Tseq / 64, BHn), 128>>>();

    gemm_bf<1><<<dim3(Cdim / 64, MROWS / 128), 256>>>(nullptr, w_proj, out,
                                                      MROWS, Cdim, Cdim);
}